// round 5
// baseline (speedup 1.0000x reference)
#include <cuda_runtime.h>

// ---------------------------------------------------------------------------
// BiSpikeNet forward. T=8, B=16, F=262144.
//
// 256 blocks x 512 threads, launch_bounds(512,2) -> 2 blocks/SM co-resident
// (64 KiB membrane SMEM each). Blocks are batch-interleaved so co-residents
// hit their per-batch barriers out of phase, keeping DRAM busy.
//
// Each pair of 512-blocks (h=0,1) reproduces one R2 1024-thread block:
// per-thread element order, warp-leaf sums, the 32-leaf XOR reduction tree
// and the sequential 8-partial batch sum are all bitwise identical to the
// passing R2 kernel, so spike decisions (and the output) match exactly.
// Spike bits in registers; counts popc'd at the end (unpacked BEFORE the
// cross-block sum -- R4's overflow bug). x[t+1] L2-prefetched pre-barrier.
// ---------------------------------------------------------------------------

namespace {
constexpr int T_STEPS        = 8;
constexpr int BATCH          = 16;
constexpr int FDIM           = 1 << 18;               // 262144
constexpr int PAIRS          = 8;                     // R2 blocks per batch
constexpr int BLKS_PER_BATCH = PAIRS * 2;             // 16
constexpr int NBLOCKS        = BATCH * BLKS_PER_BATCH;// 256
constexpr int NTHREADS       = 512;
constexpr int KG             = 8;                     // float4 groups/thread
constexpr int NHEADS         = 4;
constexpr int HID            = 64;
constexpr int NBAR           = (T_STEPS + 1) * BATCH; // 144
constexpr int SMEM_DYN       = KG * NTHREADS * 16;    // 64 KiB membrane
constexpr int F4_PER_B       = FDIM / 4;              // 65536
}

__device__ unsigned int g_bar[NBAR];
__device__ float g_invd[T_STEPS][BATCH];
__device__ float g_wsum[T_STEPS][BATCH][PAIRS][32];   // R2 warp-leaf sums
__device__ unsigned int g_cnt_part[BATCH][BLKS_PER_BATCH][4];

__global__ void reset_kernel() {
    int i = threadIdx.x;
    if (i < NBAR) g_bar[i] = 0u;
    if (i < T_STEPS * BATCH) ((float*)g_invd)[i] = 0.0f;
}

__device__ __forceinline__ void l2_prefetch(const void* p) {
    asm volatile("prefetch.global.L2 [%0];" :: "l"(p));
}

__global__ void __launch_bounds__(NTHREADS, 2) bispike_kernel(
    const float* __restrict__ x,
    const float* __restrict__ decay_p,
    const float* __restrict__ vth_p,
    const float* __restrict__ W1,
    const float* __restrict__ b1,
    const float* __restrict__ W2,
    const float* __restrict__ b2,
    const float* __restrict__ att_w,
    float* __restrict__ out)
{
    extern __shared__ float smem_dyn[];
    float4* s_m4 = reinterpret_cast<float4*>(smem_dyn);   // 4096 float4

    __shared__ float s_red[16];
    __shared__ unsigned int s_redc[16];
    __shared__ float s_h[NHEADS * HID];
    __shared__ float s_maps[32];
    __shared__ float s_aw[T_STEPS];
    __shared__ float s_invd;

    const int tid   = threadIdx.x;
    const int lane  = tid & 31;
    const int warp  = tid >> 5;
    const int b     = blockIdx.x & 15;       // batch (interleaved)
    const int pairh = blockIdx.x >> 4;       // 0..15
    const int p     = pairh >> 1;            // R2 block (pair) 0..7
    const int h     = pairh & 1;             // half within pair
    const int rtid  = h * 512 + tid;         // R2 tid 0..1023

    const float d    = 1.0f / (1.0f + expf(-decay_p[0]));
    const float vth  = vth_p[0];
    const float dvth = d * vth;

    unsigned int bits4[KG];
#pragma unroll
    for (int k = 0; k < KG; k++) bits4[k] = 0u;

    // float4 base of this pair's region for batch b (per time step added later)
    const int reg4 = b * F4_PER_B + p * 8192;
    float inv_prev = 0.0f;

    // ---------------- temporal LIF loop ----------------
    for (int t = 0; t < T_STEPS; t++) {
        const float inv = inv_prev;
        const float4* xp = reinterpret_cast<const float4*>(x)
                         + (size_t)t * BATCH * F4_PER_B + reg4;
        float sa0 = 0.f, sa1 = 0.f, sa2 = 0.f, sa3 = 0.f;
#pragma unroll
        for (int k = 0; k < KG; k++) {
            const int gidx = k * 1024 + rtid;     // R2 element index
            const int sidx = k * NTHREADS + tid;  // local SMEM index
            float4 xv = xp[gidx];
            float xa[4] = {xv.x, xv.y, xv.z, xv.w};
            float ma[4];
            if (t == 0) {
#pragma unroll
                for (int j = 0; j < 4; j++) ma[j] = xa[j];
            } else {
                float4 mo = s_m4[sidx];
                float moa[4] = {mo.x, mo.y, mo.z, mo.w};
#pragma unroll
                for (int j = 0; j < 4; j++) {
                    float mn = moa[j] * inv;
                    bool  sp = (mn >= vth);
                    if (sp) bits4[k] |= (1u << (8 * j + (t - 1)));
                    ma[j] = fmaf(d, mn, xa[j]) - (sp ? dvth : 0.0f);
                }
            }
            s_m4[sidx] = make_float4(ma[0], ma[1], ma[2], ma[3]);
            sa0 += fabsf(ma[0]); sa1 += fabsf(ma[1]);
            sa2 += fabsf(ma[2]); sa3 += fabsf(ma[3]);
        }
        float sum_abs = (sa0 + sa1) + (sa2 + sa3);

        // L2 prefetch of x[t+1] (one per 128B line)
        if (t + 1 < T_STEPS && (lane & 7) == 0) {
            const float4* xn = reinterpret_cast<const float4*>(x)
                             + (size_t)(t + 1) * BATCH * F4_PER_B + reg4;
#pragma unroll
            for (int k = 0; k < KG; k++)
                l2_prefetch(&xn[k * 1024 + rtid]);
        }

        // warp-leaf sums (identical to R2's per-warp shuffle tree)
#pragma unroll
        for (int off = 16; off > 0; off >>= 1)
            sum_abs += __shfl_xor_sync(0xffffffffu, sum_abs, off);
        if (lane == 0) s_red[warp] = sum_abs;
        __syncthreads();

        if (warp == 0) {
            unsigned int old = 0;
            if (lane == 0) {
                // publish our 16 leaves (R2 warps h*16..h*16+15)
                float4* dst = reinterpret_cast<float4*>(&g_wsum[t][b][p][h * 16]);
                const float4* src = reinterpret_cast<const float4*>(s_red);
                dst[0] = src[0]; dst[1] = src[1];
                dst[2] = src[2]; dst[3] = src[3];
                __threadfence();
                old = atomicAdd(&g_bar[t * BATCH + b], 1u);
            }
            old = __shfl_sync(0xffffffffu, old, 0);
            if (old == BLKS_PER_BATCH - 1) {
                __threadfence();
                // lanes 0..7: rebuild R2's 32-leaf XOR tree for pair=lane
                float partial = 0.0f;
                if (lane < PAIRS) {
                    float a[32];
                    const float4* ws = reinterpret_cast<const float4*>(
                        &g_wsum[t][b][lane][0]);
#pragma unroll
                    for (int i = 0; i < 8; i++) {
                        float4 v = ws[i];
                        a[4*i] = v.x; a[4*i+1] = v.y; a[4*i+2] = v.z; a[4*i+3] = v.w;
                    }
#pragma unroll
                    for (int off = 16; off > 0; off >>= 1)
#pragma unroll
                        for (int i = 0; i < 32; i++)
                            if (i < off) a[i] += a[i + off];
                    partial = a[0];
                }
                // sequential 8-partial sum, same order as R2
                float tot = 0.0f;
#pragma unroll
                for (int q = 0; q < PAIRS; q++)
                    tot += __shfl_sync(0xffffffffu, partial, q);
                if (lane == 0) {
                    float dnm = tot * (1.0f / (float)FDIM) + 1e-6f;
                    float iv  = 1.0f / dnm;
                    *(volatile float*)&g_invd[t][b] = iv;
                    s_invd = iv;
                }
            } else if (lane == 0) {
                float iv;
                do { iv = *(volatile float*)&g_invd[t][b]; } while (iv == 0.0f);
                s_invd = iv;
            }
        }
        __syncthreads();
        inv_prev = s_invd;
    }

    // ---------------- final step spikes (t = T-1) ----------------
    {
        const float inv = inv_prev;
#pragma unroll
        for (int k = 0; k < KG; k++) {
            float4 mo = s_m4[k * NTHREADS + tid];
            float moa[4] = {mo.x, mo.y, mo.z, mo.w};
#pragma unroll
            for (int j = 0; j < 4; j++)
                if (moa[j] * inv >= vth) bits4[k] |= (1u << (8 * j + 7));
        }
    }

    // ---------------- spike counts via popc (packed 2x16-bit) -------------
    {
        unsigned int packed[4];
#pragma unroll
        for (int q = 0; q < 4; q++) {
            unsigned int c_lo = 0, c_hi = 0;
            unsigned int m_lo = 0x01010101u << (2 * q);
            unsigned int m_hi = 0x01010101u << (2 * q + 1);
#pragma unroll
            for (int k = 0; k < KG; k++) {
                c_lo += __popc(bits4[k] & m_lo);
                c_hi += __popc(bits4[k] & m_hi);
            }
            packed[q] = c_lo | (c_hi << 16);     // block sum <= 16384, no overflow
        }
#pragma unroll
        for (int q = 0; q < 4; q++) {
            unsigned int v = packed[q];
#pragma unroll
            for (int off = 16; off > 0; off >>= 1)
                v += __shfl_xor_sync(0xffffffffu, v, off);
            if (lane == 0) s_redc[warp] = v;
            __syncthreads();
            if (warp == 0) {
                unsigned int c = (lane < 16) ? s_redc[lane] : 0u;
#pragma unroll
                for (int off = 8; off > 0; off >>= 1)
                    c += __shfl_xor_sync(0xffffffffu, c, off);
                if (lane == 0)
                    *(volatile unsigned int*)&g_cnt_part[b][pairh][q] = c;
            }
            __syncthreads();
        }
        if (warp == 0 && lane == 0) {
            __threadfence();
            unsigned int* bar = &g_bar[T_STEPS * BATCH + b];
            atomicAdd(bar, 1u);
            volatile unsigned int* ctr = bar;
            while (*ctr < (unsigned)BLKS_PER_BATCH) { }
        }
        __syncthreads();
    }

    // ---------------- tiny attention MLP (warp 0, per batch) --------------
    if (warp == 0) {
        float summ[T_STEPS];
#pragma unroll
        for (int q = 0; q < 4; q++) {
            unsigned int lo = 0, hi = 0;
            if (lane < BLKS_PER_BATCH) {
                unsigned int v = *(volatile unsigned int*)&g_cnt_part[b][lane][q];
                lo = v & 0xffffu;                // UNPACK BEFORE cross-block sum
                hi = v >> 16;
            }
#pragma unroll
            for (int off = 16; off > 0; off >>= 1) {
                lo += __shfl_xor_sync(0xffffffffu, lo, off);
                hi += __shfl_xor_sync(0xffffffffu, hi, off);
            }
            summ[2 * q]     = (float)lo * (1.0f / (float)FDIM);
            summ[2 * q + 1] = (float)hi * (1.0f / (float)FDIM);
        }
#pragma unroll
        for (int r = 0; r < 8; r++) {
            int idx = r * 32 + lane;
            float acc = b1[idx];
#pragma unroll
            for (int t = 0; t < T_STEPS; t++)
                acc += summ[t] * W1[idx * T_STEPS + t];
            s_h[idx] = fmaxf(acc, 0.0f);
        }
        __syncwarp();
        {
            float acc = b2[lane];
            const int hb = (lane >> 3) * HID;
            const float* w2p = W2 + lane * HID;
#pragma unroll
            for (int hd = 0; hd < HID; hd++)
                acc += s_h[hb + hd] * w2p[hd];
            s_maps[lane] = acc * att_w[lane >> 3];
        }
        __syncwarp();
        if (lane == 0) {
            float w[T_STEPS];
            float mx = -1e30f;
#pragma unroll
            for (int t = 0; t < T_STEPS; t++) {
                w[t] = s_maps[t] + s_maps[8 + t] + s_maps[16 + t] + s_maps[24 + t];
                mx = fmaxf(mx, w[t]);
            }
            float ssum = 0.0f;
#pragma unroll
            for (int t = 0; t < T_STEPS; t++) { w[t] = expf(w[t] - mx); ssum += w[t]; }
            float invs = 1.0f / ssum;
#pragma unroll
            for (int t = 0; t < T_STEPS; t++) s_aw[t] = w[t] * invs;
        }
    }
    __syncthreads();

    float aw[T_STEPS];
#pragma unroll
    for (int t = 0; t < T_STEPS; t++) aw[t] = s_aw[t];

    // ---------------- output: out[b,f] = sum_t aw[t]*spike(t,f) -----------
    float4* op = reinterpret_cast<float4*>(out) + reg4;
#pragma unroll
    for (int k = 0; k < KG; k++) {
        unsigned int bt = bits4[k];
        float o[4];
#pragma unroll
        for (int j = 0; j < 4; j++) {
            float v = 0.0f;
#pragma unroll
            for (int t = 0; t < T_STEPS; t++)
                v += ((bt >> (8 * j + t)) & 1u) ? aw[t] : 0.0f;
            o[j] = v;
        }
        op[k * 1024 + rtid] = make_float4(o[0], o[1], o[2], o[3]);
    }
}

extern "C" void kernel_launch(void* const* d_in, const int* in_sizes, int n_in,
                              void* d_out, int out_size) {
    (void)in_sizes; (void)n_in; (void)out_size;
    cudaFuncSetAttribute(bispike_kernel,
                         cudaFuncAttributeMaxDynamicSharedMemorySize, SMEM_DYN);
    reset_kernel<<<1, 256>>>();
    bispike_kernel<<<NBLOCKS, NTHREADS, SMEM_DYN>>>(
        (const float*)d_in[0],   // x
        (const float*)d_in[1],   // decay_param
        (const float*)d_in[2],   // v_th
        (const float*)d_in[3],   // W1
        (const float*)d_in[4],   // b1
        (const float*)d_in[5],   // W2
        (const float*)d_in[6],   // b2
        (const float*)d_in[7],   // att_w
        (float*)d_out);
}

// round 6
// speedup vs baseline: 1.0005x; 1.0005x over previous
#include <cuda_runtime.h>

// ---------------------------------------------------------------------------
// BiSpikeNet forward. T=8, B=16, F=262144. R2 skeleton (128 blocks x 1024
// threads, membrane in 128 KiB SMEM, per-batch 8-block software barrier),
// with: (1) full-horizon L2 prefetch of x[1..7] at t=0 (x ~ fits in L2) plus
// per-step re-assert of t+1; (2) broadcast-float barrier release (last
// arriver sums the 8 partials in R2's exact order); (3) spike counts popc'd
// from register bits at the end instead of per-step shuffle reductions.
// Denominator arithmetic is bitwise identical to the passing R2 kernel.
// ---------------------------------------------------------------------------

namespace {
constexpr int T_STEPS        = 8;
constexpr int BATCH          = 16;
constexpr int FDIM           = 1 << 18;          // 262144
constexpr int BLKS_PER_BATCH = 8;
constexpr int NBLOCKS        = BATCH * BLKS_PER_BATCH;   // 128
constexpr int NTHREADS       = 1024;
constexpr int EPB            = FDIM / BLKS_PER_BATCH;    // 32768 elems/block
constexpr int KG             = EPB / (NTHREADS * 4);     // 8 float4 groups/thread
constexpr int NHEADS         = 4;
constexpr int HID            = 64;
constexpr int NBAR           = (T_STEPS + 1) * BATCH;    // 144 counters
constexpr int SMEM_DYN       = EPB * 4;                  // 128 KiB membrane
}

__device__ unsigned int g_bar[NBAR];
__device__ float g_invd[T_STEPS][BATCH];
__device__ float g_abs_part[T_STEPS][BATCH][BLKS_PER_BATCH];
__device__ unsigned int g_cnt_part[BATCH][BLKS_PER_BATCH][4];

__global__ void reset_kernel() {
    int i = threadIdx.x;
    if (i < NBAR) g_bar[i] = 0u;
    if (i < T_STEPS * BATCH) ((float*)g_invd)[i] = 0.0f;
}

__device__ __forceinline__ void l2_prefetch(const void* p) {
    asm volatile("prefetch.global.L2 [%0];" :: "l"(p));
}

// per-batch barrier + denom broadcast; returns 1/denom. Called by (warp0,lane0).
// Summation of the 8 partials is sequential in block order == R2's order.
__device__ __forceinline__ float barrier_denom(int t, int b, int blk, float partial) {
    *(volatile float*)&g_abs_part[t][b][blk] = partial;
    __threadfence();
    unsigned old = atomicAdd(&g_bar[t * BATCH + b], 1u);
    if (old == BLKS_PER_BATCH - 1) {
        float tot = 0.0f;
        volatile float* pp = &g_abs_part[t][b][0];
#pragma unroll
        for (int i = 0; i < BLKS_PER_BATCH; i++) tot += pp[i];
        float dnm = tot * (1.0f / (float)FDIM) + 1e-6f;
        float iv  = 1.0f / dnm;
        *(volatile float*)&g_invd[t][b] = iv;
        return iv;
    }
    float iv;
    do { iv = *(volatile float*)&g_invd[t][b]; } while (iv == 0.0f);
    return iv;
}

__global__ void __launch_bounds__(NTHREADS, 1) bispike_kernel(
    const float* __restrict__ x,
    const float* __restrict__ decay_p,
    const float* __restrict__ vth_p,
    const float* __restrict__ W1,
    const float* __restrict__ b1,
    const float* __restrict__ W2,
    const float* __restrict__ b2,
    const float* __restrict__ att_w,
    float* __restrict__ out)
{
    extern __shared__ float smem_dyn[];
    float4* s_m4 = reinterpret_cast<float4*>(smem_dyn);     // EPB floats

    __shared__ float s_red[32];
    __shared__ unsigned int s_redc[32];
    __shared__ float s_h[NHEADS * HID];
    __shared__ float s_maps[32];
    __shared__ float s_aw[T_STEPS];
    __shared__ float s_invd;

    const int tid  = threadIdx.x;
    const int lane = tid & 31;
    const int warp = tid >> 5;
    const int b    = blockIdx.x >> 3;            // batch
    const int blk  = blockIdx.x & 7;             // slice within batch
    const int f0   = blk * EPB;

    const float d    = 1.0f / (1.0f + expf(-decay_p[0]));
    const float vth  = vth_p[0];
    const float dvth = d * vth;

    unsigned int bits4[KG];                      // 4 elems x 8 step-bits per word
#pragma unroll
    for (int k = 0; k < KG; k++) bits4[k] = 0u;

    const float* xbase = x + (size_t)b * FDIM + f0;
    float inv_prev = 0.0f;

    // ---------------- temporal LIF loop ----------------
    for (int t = 0; t < T_STEPS; t++) {
        const float inv = inv_prev;
        const float4* xp = reinterpret_cast<const float4*>(
            xbase + (size_t)t * BATCH * FDIM);
        float sa0 = 0.f, sa1 = 0.f, sa2 = 0.f, sa3 = 0.f;
#pragma unroll
        for (int k = 0; k < KG; k++) {
            const int idx4 = k * NTHREADS + tid;
            float4 xv = xp[idx4];
            float xa[4] = {xv.x, xv.y, xv.z, xv.w};
            float ma[4];
            if (t == 0) {
#pragma unroll
                for (int j = 0; j < 4; j++) ma[j] = xa[j];
            } else {
                float4 mo = s_m4[idx4];
                float moa[4] = {mo.x, mo.y, mo.z, mo.w};
#pragma unroll
                for (int j = 0; j < 4; j++) {
                    float mn = moa[j] * inv;        // normalized m_{t-1}
                    bool  sp = (mn >= vth);
                    if (sp) bits4[k] |= (1u << (8 * j + (t - 1)));
                    ma[j] = fmaf(d, mn, xa[j]) - (sp ? dvth : 0.0f);
                }
            }
            s_m4[idx4] = make_float4(ma[0], ma[1], ma[2], ma[3]);
            sa0 += fabsf(ma[0]); sa1 += fabsf(ma[1]);
            sa2 += fabsf(ma[2]); sa3 += fabsf(ma[3]);
        }
        float sum_abs = (sa0 + sa1) + (sa2 + sa3);

        // ---- L2 prefetch: full horizon at t=0, re-assert t+1 each step ----
        // one prefetch per 128B line: lanes 0,8,16,24 cover the warp span
        if ((lane & 7) == 0) {
            if (t == 0) {
                for (int tf = 1; tf < T_STEPS; tf++) {
                    const float4* xf = reinterpret_cast<const float4*>(
                        xbase + (size_t)tf * BATCH * FDIM);
#pragma unroll
                    for (int k = 0; k < KG; k++)
                        l2_prefetch(&xf[k * NTHREADS + tid]);
                }
            } else if (t + 1 < T_STEPS) {
                const float4* xn = reinterpret_cast<const float4*>(
                    xbase + (size_t)(t + 1) * BATCH * FDIM);
#pragma unroll
                for (int k = 0; k < KG; k++)
                    l2_prefetch(&xn[k * NTHREADS + tid]);
            }
        }

        // deterministic block reduction of |m| sum (identical to R2)
#pragma unroll
        for (int off = 16; off > 0; off >>= 1)
            sum_abs += __shfl_xor_sync(0xffffffffu, sum_abs, off);
        if (lane == 0) s_red[warp] = sum_abs;
        __syncthreads();
        if (warp == 0) {
            float v = s_red[lane];
#pragma unroll
            for (int off = 16; off > 0; off >>= 1)
                v += __shfl_xor_sync(0xffffffffu, v, off);
            if (lane == 0) s_invd = barrier_denom(t, b, blk, v);
        }
        __syncthreads();
        inv_prev = s_invd;
    }

    // ---------------- final step spikes (t = T-1) ----------------
    {
        const float inv = inv_prev;
#pragma unroll
        for (int k = 0; k < KG; k++) {
            float4 mo = s_m4[k * NTHREADS + tid];
            float moa[4] = {mo.x, mo.y, mo.z, mo.w};
#pragma unroll
            for (int j = 0; j < 4; j++)
                if (moa[j] * inv >= vth) bits4[k] |= (1u << (8 * j + 7));
        }
    }

    // ---------------- spike counts via popc (packed 2x16-bit) -------------
    {
        unsigned int packed[4];
#pragma unroll
        for (int q = 0; q < 4; q++) {
            unsigned int c_lo = 0, c_hi = 0;
            unsigned int m_lo = 0x01010101u << (2 * q);
            unsigned int m_hi = 0x01010101u << (2 * q + 1);
#pragma unroll
            for (int k = 0; k < KG; k++) {
                c_lo += __popc(bits4[k] & m_lo);
                c_hi += __popc(bits4[k] & m_hi);
            }
            packed[q] = c_lo | (c_hi << 16);     // block count <= 32768: fits
        }
#pragma unroll
        for (int q = 0; q < 4; q++) {
            unsigned int v = packed[q];
#pragma unroll
            for (int off = 16; off > 0; off >>= 1)
                v += __shfl_xor_sync(0xffffffffu, v, off);
            if (lane == 0) s_redc[warp] = v;
            __syncthreads();
            if (warp == 0) {
                unsigned int c = s_redc[lane];
#pragma unroll
                for (int off = 16; off > 0; off >>= 1)
                    c += __shfl_xor_sync(0xffffffffu, c, off);
                if (lane == 0)
                    *(volatile unsigned int*)&g_cnt_part[b][blk][q] = c;
            }
            __syncthreads();
        }
        if (warp == 0 && lane == 0) {
            __threadfence();
            unsigned int* bar = &g_bar[T_STEPS * BATCH + b];
            atomicAdd(bar, 1u);
            volatile unsigned int* ctr = bar;
            while (*ctr < (unsigned)BLKS_PER_BATCH) { }
        }
        __syncthreads();
    }

    // ---------------- tiny attention MLP (warp 0, per batch) --------------
    if (warp == 0) {
        float summ[T_STEPS];
#pragma unroll
        for (int q = 0; q < 4; q++) {
            unsigned int lo = 0, hi = 0;
            if (lane < BLKS_PER_BATCH) {
                unsigned int v = *(volatile unsigned int*)&g_cnt_part[b][lane][q];
                lo = v & 0xffffu;                 // unpack BEFORE cross-block sum
                hi = v >> 16;
            }
#pragma unroll
            for (int off = 16; off > 0; off >>= 1) {
                lo += __shfl_xor_sync(0xffffffffu, lo, off);
                hi += __shfl_xor_sync(0xffffffffu, hi, off);
            }
            summ[2 * q]     = (float)lo * (1.0f / (float)FDIM);
            summ[2 * q + 1] = (float)hi * (1.0f / (float)FDIM);
        }
#pragma unroll
        for (int r = 0; r < 8; r++) {
            int idx = r * 32 + lane;
            float acc = b1[idx];
#pragma unroll
            for (int t = 0; t < T_STEPS; t++)
                acc += summ[t] * W1[idx * T_STEPS + t];
            s_h[idx] = fmaxf(acc, 0.0f);
        }
        __syncwarp();
        {
            float acc = b2[lane];
            const int hb = (lane >> 3) * HID;
            const float* w2p = W2 + lane * HID;
#pragma unroll
            for (int hd = 0; hd < HID; hd++)
                acc += s_h[hb + hd] * w2p[hd];
            s_maps[lane] = acc * att_w[lane >> 3];
        }
        __syncwarp();
        if (lane == 0) {
            float w[T_STEPS];
            float mx = -1e30f;
#pragma unroll
            for (int t = 0; t < T_STEPS; t++) {
                w[t] = s_maps[t] + s_maps[8 + t] + s_maps[16 + t] + s_maps[24 + t];
                mx = fmaxf(mx, w[t]);
            }
            float ssum = 0.0f;
#pragma unroll
            for (int t = 0; t < T_STEPS; t++) { w[t] = expf(w[t] - mx); ssum += w[t]; }
            float invs = 1.0f / ssum;
#pragma unroll
            for (int t = 0; t < T_STEPS; t++) s_aw[t] = w[t] * invs;
        }
    }
    __syncthreads();

    float aw[T_STEPS];
#pragma unroll
    for (int t = 0; t < T_STEPS; t++) aw[t] = s_aw[t];

    // ---------------- output: out[b,f] = sum_t aw[t]*spike(t,f) -----------
    float4* op = reinterpret_cast<float4*>(out + (size_t)b * FDIM + f0);
#pragma unroll
    for (int k = 0; k < KG; k++) {
        unsigned int bt = bits4[k];
        float o[4];
#pragma unroll
        for (int j = 0; j < 4; j++) {
            float v = 0.0f;
#pragma unroll
            for (int t = 0; t < T_STEPS; t++)
                v += ((bt >> (8 * j + t)) & 1u) ? aw[t] : 0.0f;
            o[j] = v;
        }
        op[k * NTHREADS + tid] = make_float4(o[0], o[1], o[2], o[3]);
    }
}

extern "C" void kernel_launch(void* const* d_in, const int* in_sizes, int n_in,
                              void* d_out, int out_size) {
    (void)in_sizes; (void)n_in; (void)out_size;
    cudaFuncSetAttribute(bispike_kernel,
                         cudaFuncAttributeMaxDynamicSharedMemorySize, SMEM_DYN);
    reset_kernel<<<1, 256>>>();
    bispike_kernel<<<NBLOCKS, NTHREADS, SMEM_DYN>>>(
        (const float*)d_in[0],   // x
        (const float*)d_in[1],   // decay_param
        (const float*)d_in[2],   // v_th
        (const float*)d_in[3],   // W1
        (const float*)d_in[4],   // b1
        (const float*)d_in[5],   // W2
        (const float*)d_in[6],   // b2
        (const float*)d_in[7],   // att_w
        (float*)d_out);
}

// round 7
// speedup vs baseline: 1.1032x; 1.1026x over previous
#include <cuda_runtime.h>

// ---------------------------------------------------------------------------
// BiSpikeNet forward. T=8, B=16, F=262144.
//
// 128 blocks x 512 threads (regs/thread cap = 128). Each thread owns 64
// elements: membrane in SMEM (thread-private spill space, 128 KiB), and
// x[t+1] held in 16 float4 REGISTERS across the per-batch barrier -- the
// LDGs for step t+1 are issued inside step t's compute loop, so DRAM
// latency+bandwidth stream in the barrier/reduce shadow. No prefetch ops.
// Barrier is R2-style: counter spin, every block reads the 8 partials and
// computes the denominator itself (sequential, deterministic order).
// Spike bits in registers; counts popc'd at the end.
// ---------------------------------------------------------------------------

namespace {
constexpr int T_STEPS        = 8;
constexpr int BATCH          = 16;
constexpr int FDIM           = 1 << 18;          // 262144
constexpr int BLKS_PER_BATCH = 8;
constexpr int NBLOCKS        = BATCH * BLKS_PER_BATCH;   // 128
constexpr int NTHREADS       = 512;
constexpr int NWARPS         = NTHREADS / 32;            // 16
constexpr int EPB            = FDIM / BLKS_PER_BATCH;    // 32768 elems/block
constexpr int KG             = EPB / (NTHREADS * 4);     // 16 float4/thread
constexpr int NHEADS         = 4;
constexpr int HID            = 64;
constexpr int NBAR           = (T_STEPS + 1) * BATCH;    // 144 counters
constexpr int SMEM_DYN       = EPB * 4;                  // 128 KiB membrane
}

__device__ unsigned int g_bar[NBAR];
__device__ float g_abs_part[T_STEPS][BATCH][BLKS_PER_BATCH];
__device__ unsigned int g_cnt_part[BATCH][BLKS_PER_BATCH][4];

__global__ void reset_kernel() {
    int i = threadIdx.x;
    if (i < NBAR) g_bar[i] = 0u;
}

__global__ void __launch_bounds__(NTHREADS, 1) bispike_kernel(
    const float* __restrict__ x,
    const float* __restrict__ decay_p,
    const float* __restrict__ vth_p,
    const float* __restrict__ W1,
    const float* __restrict__ b1,
    const float* __restrict__ W2,
    const float* __restrict__ b2,
    const float* __restrict__ att_w,
    float* __restrict__ out)
{
    extern __shared__ float smem_dyn[];
    float4* s_m4 = reinterpret_cast<float4*>(smem_dyn);   // 8192 float4

    __shared__ float s_red[NWARPS];
    __shared__ unsigned int s_redc[NWARPS];
    __shared__ float s_h[NHEADS * HID];
    __shared__ float s_maps[32];
    __shared__ float s_aw[T_STEPS];
    __shared__ float s_invd;

    const int tid  = threadIdx.x;
    const int lane = tid & 31;
    const int warp = tid >> 5;
    const int b    = blockIdx.x >> 3;            // batch
    const int blk  = blockIdx.x & 7;             // slice within batch
    const int f0   = blk * EPB;

    const float d    = 1.0f / (1.0f + expf(-decay_p[0]));
    const float vth  = vth_p[0];
    const float dvth = d * vth;

    unsigned int bits4[KG];                      // 4 elems x 8 step-bits per word
#pragma unroll
    for (int k = 0; k < KG; k++) bits4[k] = 0u;

    const float* xbase = x + (size_t)b * FDIM + f0;

    // ---------------- prologue: load x[0] into registers ----------------
    float4 xr[KG];
    {
        const float4* xp0 = reinterpret_cast<const float4*>(xbase);
#pragma unroll
        for (int k = 0; k < KG; k++)
            xr[k] = xp0[k * NTHREADS + tid];
    }

    float inv_prev = 0.0f;

    // ---------------- temporal LIF loop ----------------
#pragma unroll
    for (int t = 0; t < T_STEPS; t++) {
        const float inv = inv_prev;
        const float4* xn4 = reinterpret_cast<const float4*>(
            xbase + (size_t)(t + 1) * BATCH * FDIM);   // used only if t<7
        float sa0 = 0.f, sa1 = 0.f, sa2 = 0.f, sa3 = 0.f;
#pragma unroll
        for (int k = 0; k < KG; k++) {
            const int idx4 = k * NTHREADS + tid;
            float4 xv = xr[k];
            float xa[4] = {xv.x, xv.y, xv.z, xv.w};
            float ma[4];
            if (t == 0) {
#pragma unroll
                for (int j = 0; j < 4; j++) ma[j] = xa[j];
            } else {
                float4 mo = s_m4[idx4];
                float moa[4] = {mo.x, mo.y, mo.z, mo.w};
#pragma unroll
                for (int j = 0; j < 4; j++) {
                    float mn = moa[j] * inv;        // normalized m_{t-1}
                    bool  sp = (mn >= vth);
                    if (sp) bits4[k] |= (1u << (8 * j + (t - 1)));
                    ma[j] = fmaf(d, mn, xa[j]) - (sp ? dvth : 0.0f);
                }
            }
            s_m4[idx4] = make_float4(ma[0], ma[1], ma[2], ma[3]);
            sa0 += fabsf(ma[0]); sa1 += fabsf(ma[1]);
            sa2 += fabsf(ma[2]); sa3 += fabsf(ma[3]);
            // issue next step's load NOW; consumed after the barrier
            if (t + 1 < T_STEPS)
                xr[k] = xn4[idx4];
        }
        float sum_abs = (sa0 + sa1) + (sa2 + sa3);

        // deterministic block reduction of |m| sum (16 warp leaves)
#pragma unroll
        for (int off = 16; off > 0; off >>= 1)
            sum_abs += __shfl_xor_sync(0xffffffffu, sum_abs, off);
        if (lane == 0) s_red[warp] = sum_abs;
        __syncthreads();
        if (warp == 0) {
            float v = (lane < NWARPS) ? s_red[lane] : 0.0f;
#pragma unroll
            for (int off = 8; off > 0; off >>= 1)
                v += __shfl_xor_sync(0xffffffffu, v, off);
            if (lane == 0) {
                // R2-style barrier: publish partial, spin on counter,
                // then sum all 8 partials locally (deterministic order).
                *(volatile float*)&g_abs_part[t][b][blk] = v;
                __threadfence();
                unsigned int* bar = &g_bar[t * BATCH + b];
                atomicAdd(bar, 1u);
                volatile unsigned int* ctr = bar;
                while (*ctr < (unsigned)BLKS_PER_BATCH) { }
                volatile float* pp = &g_abs_part[t][b][0];
                float tot = 0.0f;
#pragma unroll
                for (int i = 0; i < BLKS_PER_BATCH; i++) tot += pp[i];
                float dnm = tot * (1.0f / (float)FDIM) + 1e-6f;
                s_invd = 1.0f / dnm;
            }
        }
        __syncthreads();
        inv_prev = s_invd;
    }

    // ---------------- final step spikes (t = T-1) ----------------
    {
        const float inv = inv_prev;
#pragma unroll
        for (int k = 0; k < KG; k++) {
            float4 mo = s_m4[k * NTHREADS + tid];
            float moa[4] = {mo.x, mo.y, mo.z, mo.w};
#pragma unroll
            for (int j = 0; j < 4; j++)
                if (moa[j] * inv >= vth) bits4[k] |= (1u << (8 * j + 7));
        }
    }

    // ---------------- spike counts via popc (packed 2x16-bit) -------------
    {
        unsigned int packed[4];
#pragma unroll
        for (int q = 0; q < 4; q++) {
            unsigned int c_lo = 0, c_hi = 0;
            unsigned int m_lo = 0x01010101u << (2 * q);
            unsigned int m_hi = 0x01010101u << (2 * q + 1);
#pragma unroll
            for (int k = 0; k < KG; k++) {
                c_lo += __popc(bits4[k] & m_lo);
                c_hi += __popc(bits4[k] & m_hi);
            }
            packed[q] = c_lo | (c_hi << 16);     // block count <= 32768: fits
        }
#pragma unroll
        for (int q = 0; q < 4; q++) {
            unsigned int v = packed[q];
#pragma unroll
            for (int off = 16; off > 0; off >>= 1)
                v += __shfl_xor_sync(0xffffffffu, v, off);
            if (lane == 0) s_redc[warp] = v;
            __syncthreads();
            if (warp == 0) {
                unsigned int c = (lane < NWARPS) ? s_redc[lane] : 0u;
#pragma unroll
                for (int off = 8; off > 0; off >>= 1)
                    c += __shfl_xor_sync(0xffffffffu, c, off);
                if (lane == 0)
                    *(volatile unsigned int*)&g_cnt_part[b][blk][q] = c;
            }
            __syncthreads();
        }
        if (warp == 0 && lane == 0) {
            __threadfence();
            unsigned int* bar = &g_bar[T_STEPS * BATCH + b];
            atomicAdd(bar, 1u);
            volatile unsigned int* ctr = bar;
            while (*ctr < (unsigned)BLKS_PER_BATCH) { }
        }
        __syncthreads();
    }

    // ---------------- tiny attention MLP (warp 0, per batch) --------------
    if (warp == 0) {
        float summ[T_STEPS];
#pragma unroll
        for (int q = 0; q < 4; q++) {
            unsigned int lo = 0, hi = 0;
            if (lane < BLKS_PER_BATCH) {
                unsigned int v = *(volatile unsigned int*)&g_cnt_part[b][lane][q];
                lo = v & 0xffffu;                 // unpack BEFORE cross-block sum
                hi = v >> 16;
            }
#pragma unroll
            for (int off = 16; off > 0; off >>= 1) {
                lo += __shfl_xor_sync(0xffffffffu, lo, off);
                hi += __shfl_xor_sync(0xffffffffu, hi, off);
            }
            summ[2 * q]     = (float)lo * (1.0f / (float)FDIM);
            summ[2 * q + 1] = (float)hi * (1.0f / (float)FDIM);
        }
#pragma unroll
        for (int r = 0; r < 8; r++) {
            int idx = r * 32 + lane;
            float acc = b1[idx];
#pragma unroll
            for (int t = 0; t < T_STEPS; t++)
                acc += summ[t] * W1[idx * T_STEPS + t];
            s_h[idx] = fmaxf(acc, 0.0f);
        }
        __syncwarp();
        {
            float acc = b2[lane];
            const int hb = (lane >> 3) * HID;
            const float* w2p = W2 + lane * HID;
#pragma unroll
            for (int hd = 0; hd < HID; hd++)
                acc += s_h[hb + hd] * w2p[hd];
            s_maps[lane] = acc * att_w[lane >> 3];
        }
        __syncwarp();
        if (lane == 0) {
            float w[T_STEPS];
            float mx = -1e30f;
#pragma unroll
            for (int t = 0; t < T_STEPS; t++) {
                w[t] = s_maps[t] + s_maps[8 + t] + s_maps[16 + t] + s_maps[24 + t];
                mx = fmaxf(mx, w[t]);
            }
            float ssum = 0.0f;
#pragma unroll
            for (int t = 0; t < T_STEPS; t++) { w[t] = expf(w[t] - mx); ssum += w[t]; }
            float invs = 1.0f / ssum;
#pragma unroll
            for (int t = 0; t < T_STEPS; t++) s_aw[t] = w[t] * invs;
        }
    }
    __syncthreads();

    float aw[T_STEPS];
#pragma unroll
    for (int t = 0; t < T_STEPS; t++) aw[t] = s_aw[t];

    // ---------------- output: out[b,f] = sum_t aw[t]*spike(t,f) -----------
    float4* op = reinterpret_cast<float4*>(out + (size_t)b * FDIM + f0);
#pragma unroll
    for (int k = 0; k < KG; k++) {
        unsigned int bt = bits4[k];
        float o[4];
#pragma unroll
        for (int j = 0; j < 4; j++) {
            float v = 0.0f;
#pragma unroll
            for (int t = 0; t < T_STEPS; t++)
                v += ((bt >> (8 * j + t)) & 1u) ? aw[t] : 0.0f;
            o[j] = v;
        }
        op[k * NTHREADS + tid] = make_float4(o[0], o[1], o[2], o[3]);
    }
}

extern "C" void kernel_launch(void* const* d_in, const int* in_sizes, int n_in,
                              void* d_out, int out_size) {
    (void)in_sizes; (void)n_in; (void)out_size;
    cudaFuncSetAttribute(bispike_kernel,
                         cudaFuncAttributeMaxDynamicSharedMemorySize, SMEM_DYN);
    reset_kernel<<<1, 256>>>();
    bispike_kernel<<<NBLOCKS, NTHREADS, SMEM_DYN>>>(
        (const float*)d_in[0],   // x
        (const float*)d_in[1],   // decay_param
        (const float*)d_in[2],   // v_th
        (const float*)d_in[3],   // W1
        (const float*)d_in[4],   // b1
        (const float*)d_in[5],   // W2
        (const float*)d_in[6],   // b2
        (const float*)d_in[7],   // att_w
        (float*)d_out);
}